// round 15
// baseline (speedup 1.0000x reference)
#include <cuda_runtime.h>
#include <cuda_fp16.h>
#include <cstdint>

// ============================================================================
// out[M,N] = float( sum_k x[m,k]*w[n,k] ) + rint(bias[n])
// M=8192, N=4096, K=4096.  Inputs delivered widened to int32.
// fp16 HMMA path: mma.sync.m16n8k16.f32 (rt_SMSP=8); fp32 accumulation exact.
// R15 EXPERIMENT: occupancy 4 -> 6 warps/SMSP. CTA tile 128x64, 256 thr,
// warp tile 32x32, 3 stages (74KB smem), 3 CTAs/SM, <=85 regs. Keeps late
// barrier, cross-barrier t0 prefetch, per-warp kk rotation.
// ============================================================================

#define K_DIM 4096
#define N_DIM 4096
#define M_DIM 8192
#define M_TILE 128
#define N_TILE 64
#define K_ELE  64                     // K elements per stage (= 128B rows)
#define STAGES 3
#define K_ITERS (K_DIM / K_ELE)       // 64
#define NTHREADS 256

#define A_STAGE_BYTES (M_TILE * 128)  // 16384
#define B_STAGE_BYTES (N_TILE * 128)  // 8192
#define SM_A 0
#define SM_B (STAGES * A_STAGE_BYTES)                 // 49152
#define SM_RBIAS (SM_B + STAGES * B_STAGE_BYTES)      // 73728
#define SMEM_TOTAL (SM_RBIAS + N_TILE * 4)            // 73984

__device__ __half g_xh[(size_t)M_DIM * K_DIM];        // 64 MB
__device__ __half g_wh[(size_t)N_DIM * K_DIM];        // 32 MB

// ---------------------------------------------------------------- helpers
__device__ __forceinline__ uint32_t smem_u32(const void* p) {
    uint32_t a;
    asm("{ .reg .u64 t; cvta.to.shared.u64 t, %1; cvt.u32.u64 %0, t; }"
        : "=r"(a) : "l"(p));
    return a;
}
__device__ __forceinline__ void cp16(uint32_t smem_dst, const void* gmem_src) {
    asm volatile("cp.async.cg.shared.global [%0], [%1], 16;"
                 :: "r"(smem_dst), "l"(gmem_src));
}
__device__ __forceinline__ void cp_commit() {
    asm volatile("cp.async.commit_group;" ::: "memory");
}
__device__ __forceinline__ void cp_wait0() {
    asm volatile("cp.async.wait_group 0;" ::: "memory");
}
__device__ __forceinline__ void ldsm4(uint32_t r[4], uint32_t addr) {
    asm volatile("ldmatrix.sync.aligned.m8n8.x4.shared.b16 {%0,%1,%2,%3}, [%4];"
                 : "=r"(r[0]), "=r"(r[1]), "=r"(r[2]), "=r"(r[3])
                 : "r"(addr));
}
__device__ __forceinline__ void mma_f16(float d[4], const uint32_t a[4],
                                        uint32_t b0, uint32_t b1) {
    asm volatile(
        "mma.sync.aligned.m16n8k16.row.col.f32.f16.f16.f32 "
        "{%0,%1,%2,%3}, {%4,%5,%6,%7}, {%8,%9}, {%0,%1,%2,%3};"
        : "+f"(d[0]), "+f"(d[1]), "+f"(d[2]), "+f"(d[3])
        : "r"(a[0]), "r"(a[1]), "r"(a[2]), "r"(a[3]), "r"(b0), "r"(b1));
}

// ---------------------------------------------------------------- pack
__global__ void __launch_bounds__(256)
pack_s32_to_f16(const int* __restrict__ xsrc, const int* __restrict__ wsrc,
                __half* __restrict__ xdst, __half* __restrict__ wdst,
                int n8x, int n8_total) {
    int i = blockIdx.x * blockDim.x + threadIdx.x;
    if (i >= n8_total) return;
    const int* src; __half* dst; int idx;
    if (i < n8x) { src = xsrc; dst = xdst; idx = i; }
    else         { src = wsrc; dst = wdst; idx = i - n8x; }
    const int4* s = reinterpret_cast<const int4*>(src) + (size_t)idx * 2;
    int4 v0 = __ldg(&s[0]);
    int4 v1 = __ldg(&s[1]);
    uint32_t p[4];
    #define PK(lo_, hi_) \
        ((uint32_t)__half_as_ushort(__int2half_rn(lo_)) | \
         ((uint32_t)__half_as_ushort(__int2half_rn(hi_)) << 16))
    p[0] = PK(v0.x, v0.y);
    p[1] = PK(v0.z, v0.w);
    p[2] = PK(v1.x, v1.y);
    p[3] = PK(v1.z, v1.w);
    #undef PK
    reinterpret_cast<uint4*>(dst)[idx] = make_uint4(p[0], p[1], p[2], p[3]);
}

// ---------------------------------------------------------------- GEMM
// 8 warps: 4 in M (32 rows) x 2 in N (32 cols).  Warp tile 32x32.
__global__ void __launch_bounds__(NTHREADS, 3)
w8a8_hmma_kernel(const float* __restrict__ bias, float* __restrict__ out) {
    extern __shared__ char smem[];
    const uint32_t sb = smem_u32(smem);
    const int tid  = threadIdx.x;
    const int wid  = tid >> 5;
    const int lane = tid & 31;

    const int n0 = blockIdx.x * N_TILE;
    const int m0 = blockIdx.y * M_TILE;

    float* rbias = reinterpret_cast<float*>(smem + SM_RBIAS);
    for (int j = tid; j < N_TILE; j += NTHREADS)
        rbias[j] = rintf(__ldg(&bias[n0 + j]));

    // ---- bases ----------------------------------------------------------
    const int wm = (wid & 3) * 32;          // M offset within tile
    const int wn = (wid >> 2) * 32;         // N offset within tile
    const int lrow = lane & 15;
    const uint32_t x7    = (uint32_t)((lane & 7) << 4);
    const uint32_t lch16 = (uint32_t)((lane >> 4) << 4);

    const uint32_t aBase = sb + SM_A + (uint32_t)((wm + lrow) * 128);
    const uint32_t bBase = sb + SM_B + (uint32_t)((wn + lrow) * 128);

    // per-warp k16 rotation (exact addition reorder)
    const int rot = wid & 3;
    uint32_t cxr[4];
    #pragma unroll
    for (int j = 0; j < 4; j++)
        cxr[j] = ((((uint32_t)((j + rot) & 3)) << 5) | lch16) ^ x7;

    // cp.async bases: thread handles rows row0+32i, fixed chunk c0
    const int row0 = tid >> 3, c0 = tid & 7;
    const uint32_t swz0 = (uint32_t)(row0 * 128 + ((c0 ^ (row0 & 7)) << 4));
    const uint32_t dstA0 = sb + SM_A + swz0;      // B dst = dstA0 + SM_B imm
    const __half* srcA0 = g_xh + (size_t)(m0 + row0) * K_DIM + c0 * 8;
    const __half* srcB0 = g_wh + (size_t)(n0 + row0) * K_DIM + c0 * 8;

    // A: 128 rows -> 4 iters; B: 64 rows -> 2 iters
    #define LOAD_STAGE_S(s_, kofs_) do {                                      \
        _Pragma("unroll")                                                     \
        for (int i_ = 0; i_ < 4; i_++)                                        \
            cp16(dstA0 + (uint32_t)((s_) * A_STAGE_BYTES + i_ * 4096),        \
                 srcA0 + (kofs_) + i_ * 131072);                              \
        _Pragma("unroll")                                                     \
        for (int i_ = 0; i_ < 2; i_++)                                        \
            cp16(dstA0 + (uint32_t)(SM_B + (s_) * B_STAGE_BYTES + i_ * 4096), \
                 srcB0 + (kofs_) + i_ * 131072);                              \
        cp_commit();                                                          \
    } while (0)

    float acc[2][4][4];
    #pragma unroll
    for (int mi = 0; mi < 2; mi++)
        #pragma unroll
        for (int ni = 0; ni < 4; ni++)
            #pragma unroll
            for (int r = 0; r < 4; r++) acc[mi][ni][r] = 0.f;

    uint32_t afr[2][2][4];      // ping-pong x 2 mi-blocks
    uint32_t bfr[2][2][4];      // ping-pong x 2 nj-groups

    #define LOAD_A2(ab_, s_, j_) do {                                         \
        ldsm4(afr[ab_][0], aBase + cxr[j_] +                                  \
              (uint32_t)((s_) * A_STAGE_BYTES + 0 * 2048));                   \
        ldsm4(afr[ab_][1], aBase + cxr[j_] +                                  \
              (uint32_t)((s_) * A_STAGE_BYTES + 1 * 2048));                   \
    } while (0)
    #define LOAD_B2(bb_, s_, j_) do {                                         \
        ldsm4(bfr[bb_][0], bBase + cxr[j_] +                                  \
              (uint32_t)((s_) * B_STAGE_BYTES + 0 * 2048));                   \
        ldsm4(bfr[bb_][1], bBase + cxr[j_] +                                  \
              (uint32_t)((s_) * B_STAGE_BYTES + 1 * 2048));                   \
    } while (0)

    // one k16 sub-iteration: prefetch next kk's frags (or next stage's t0),
    // then 8 MMAs (2 mi x 4 ni).
    #define SUBIT(t_, s_, sn_, pf_) do {                                      \
        const int b_ = (t_) & 1;                                              \
        if ((t_) < 3) {                                                       \
            LOAD_A2(b_ ^ 1, s_, (t_) + 1);                                    \
            LOAD_B2(b_ ^ 1, s_, (t_) + 1);                                    \
        } else if (pf_) {                                                     \
            LOAD_A2(b_ ^ 1, sn_, 0);                                          \
            LOAD_B2(b_ ^ 1, sn_, 0);                                          \
        }                                                                     \
        _Pragma("unroll")                                                     \
        for (int mi_ = 0; mi_ < 2; mi_++)                                     \
            _Pragma("unroll")                                                 \
            for (int ni_ = 0; ni_ < 4; ni_++)                                 \
                mma_f16(acc[mi_][ni_], afr[b_][mi_],                          \
                        bfr[b_][ni_ >> 1][ni_ & 1],                           \
                        bfr[b_][ni_ >> 1][(ni_ & 1) + 2]);                    \
    } while (0)

    // ---- prologue --------------------------------------------------------
    LOAD_STAGE_S(0, 0);
    LOAD_STAGE_S(1, K_ELE);
    cp_wait0();
    __syncthreads();
    LOAD_A2(0, 0, 0);
    LOAD_B2(0, 0, 0);

    // ---- main loop: ks = 0..62 (unrolled by 3), tail ks = 63 --------------
    // Late barrier: subits 0..2 read stage j (published last iter); the
    // wait0+sync protect the cp16 overwrite of stage (j+2)%3 and the t=3
    // prefetch of stage (j+1)%3.
    int kload = 2 * K_ELE;
    for (int kb = 0; kb < (K_ITERS - 1) / 3; kb++) {
        #pragma unroll
        for (int j = 0; j < 3; j++) {
            SUBIT(0, j, (j + 1) % 3, 1);
            SUBIT(1, j, (j + 1) % 3, 1);
            SUBIT(2, j, (j + 1) % 3, 1);
            cp_wait0();
            __syncthreads();
            if (kload < K_DIM) {
                LOAD_STAGE_S((j + 2) % 3, kload);
                kload += K_ELE;
            }
            SUBIT(3, j, (j + 1) % 3, 1);
        }
    }
    // tail: ks = 63, stage 0 (t0 frags prefetched at ks=62's subit 3)
    SUBIT(0, 0, 1, 0);
    SUBIT(1, 0, 1, 0);
    SUBIT(2, 0, 1, 0);
    SUBIT(3, 0, 1, 0);

    // epilogue: c0,c1 at (row=lane>>2, col=(lane&3)*2+{0,1}); c2,c3 at row+8
    const int erow = lane >> 2;
    const int ecol = (lane & 3) * 2;
    #pragma unroll
    for (int mi = 0; mi < 2; mi++) {
        #pragma unroll
        for (int ni = 0; ni < 4; ni++) {
            const int gc = wn + ni * 8 + ecol;
            const float b0 = rbias[gc], b1 = rbias[gc + 1];
            {
                const int gr = m0 + wm + mi * 16 + erow;
                float2 v;
                v.x = acc[mi][ni][0] + b0;
                v.y = acc[mi][ni][1] + b1;
                *reinterpret_cast<float2*>(out + (size_t)gr * N_DIM + n0 + gc) = v;
            }
            {
                const int gr = m0 + wm + mi * 16 + 8 + erow;
                float2 v;
                v.x = acc[mi][ni][2] + b0;
                v.y = acc[mi][ni][3] + b1;
                *reinterpret_cast<float2*>(out + (size_t)gr * N_DIM + n0 + gc) = v;
            }
        }
    }
}

// ---------------------------------------------------------------- launch
extern "C" void kernel_launch(void* const* d_in, const int* in_sizes, int n_in,
                              void* d_out, int out_size) {
    int xi = 0, bi = 0;
    for (int i = 1; i < n_in; i++) {
        if (in_sizes[i] > in_sizes[xi]) xi = i;
        if (in_sizes[i] < in_sizes[bi]) bi = i;
    }
    int wi = 3 - xi - bi;

    const int*   x32  = (const int*)d_in[xi];
    const int*   w32  = (const int*)d_in[wi];
    const float* bias = (const float*)d_in[bi];
    float* out = (float*)d_out;

    __half* xh = nullptr; cudaGetSymbolAddress((void**)&xh, g_xh);
    __half* wh = nullptr; cudaGetSymbolAddress((void**)&wh, g_wh);

    const int n8x = (M_DIM * K_DIM) / 8;
    const int n8w = (N_DIM * K_DIM) / 8;
    const int n8t = n8x + n8w;
    pack_s32_to_f16<<<(n8t + 255) / 256, 256>>>(x32, w32, xh, wh, n8x, n8t);

    cudaFuncSetAttribute(w8a8_hmma_kernel,
                         cudaFuncAttributeMaxDynamicSharedMemorySize, SMEM_TOTAL);

    dim3 grid(N_DIM / N_TILE, M_DIM / M_TILE);         // (64, 64) = 4096 CTAs
    w8a8_hmma_kernel<<<grid, NTHREADS, SMEM_TOTAL>>>(bias, out);
}

// round 16
// speedup vs baseline: 1.2078x; 1.2078x over previous
#include <cuda_runtime.h>
#include <cuda_fp16.h>
#include <cstdint>

// ============================================================================
// out[M,N] = float( sum_k x[m,k]*w[n,k] ) + rint(bias[n])
// M=8192, N=4096, K=4096.  Inputs delivered widened to int32.
// fp16 HMMA path: mma.sync.m16n8k16.f32 (rt_SMSP=8); fp32 accumulation exact.
// R16: CTA tile 64x128, 128 thr (4 warps), warp tile 32x64, 3 CTAs/SM.
//  - LDSM:MMA ratio kept at 6:16 while cutting per-SM smem traffic 25%
//    (A/B fragment redundancy 2x/2x vs R14's 4x/2x).
//  - 3 small staggered barrier domains per SM instead of one 16-warp domain.
//  - keeps late barrier, cross-barrier t0 prefetch, per-warp kk rotation.
// ============================================================================

#define K_DIM 4096
#define N_DIM 4096
#define M_DIM 8192
#define M_TILE 64
#define N_TILE 128
#define K_ELE  64                     // K elements per stage (= 128B rows)
#define STAGES 3
#define K_ITERS (K_DIM / K_ELE)       // 64
#define NTHREADS 128

#define A_STAGE_BYTES (M_TILE * 128)  // 8192
#define B_STAGE_BYTES (N_TILE * 128)  // 16384
#define SM_A 0
#define SM_B (STAGES * A_STAGE_BYTES)                 // 24576
#define SM_RBIAS (SM_B + STAGES * B_STAGE_BYTES)      // 73728
#define SMEM_TOTAL (SM_RBIAS + N_TILE * 4)            // 74240 (3 CTAs = 217.5KB)

__device__ __half g_xh[(size_t)M_DIM * K_DIM];        // 64 MB
__device__ __half g_wh[(size_t)N_DIM * K_DIM];        // 32 MB

// ---------------------------------------------------------------- helpers
__device__ __forceinline__ uint32_t smem_u32(const void* p) {
    uint32_t a;
    asm("{ .reg .u64 t; cvta.to.shared.u64 t, %1; cvt.u32.u64 %0, t; }"
        : "=r"(a) : "l"(p));
    return a;
}
__device__ __forceinline__ void cp16(uint32_t smem_dst, const void* gmem_src) {
    asm volatile("cp.async.cg.shared.global [%0], [%1], 16;"
                 :: "r"(smem_dst), "l"(gmem_src));
}
__device__ __forceinline__ void cp_commit() {
    asm volatile("cp.async.commit_group;" ::: "memory");
}
__device__ __forceinline__ void cp_wait0() {
    asm volatile("cp.async.wait_group 0;" ::: "memory");
}
__device__ __forceinline__ void ldsm4(uint32_t r[4], uint32_t addr) {
    asm volatile("ldmatrix.sync.aligned.m8n8.x4.shared.b16 {%0,%1,%2,%3}, [%4];"
                 : "=r"(r[0]), "=r"(r[1]), "=r"(r[2]), "=r"(r[3])
                 : "r"(addr));
}
__device__ __forceinline__ void mma_f16(float d[4], const uint32_t a[4],
                                        uint32_t b0, uint32_t b1) {
    asm volatile(
        "mma.sync.aligned.m16n8k16.row.col.f32.f16.f16.f32 "
        "{%0,%1,%2,%3}, {%4,%5,%6,%7}, {%8,%9}, {%0,%1,%2,%3};"
        : "+f"(d[0]), "+f"(d[1]), "+f"(d[2]), "+f"(d[3])
        : "r"(a[0]), "r"(a[1]), "r"(a[2]), "r"(a[3]), "r"(b0), "r"(b1));
}

// ---------------------------------------------------------------- pack
__global__ void __launch_bounds__(256)
pack_s32_to_f16(const int* __restrict__ xsrc, const int* __restrict__ wsrc,
                __half* __restrict__ xdst, __half* __restrict__ wdst,
                int n8x, int n8_total) {
    int i = blockIdx.x * blockDim.x + threadIdx.x;
    if (i >= n8_total) return;
    const int* src; __half* dst; int idx;
    if (i < n8x) { src = xsrc; dst = xdst; idx = i; }
    else         { src = wsrc; dst = wdst; idx = i - n8x; }
    const int4* s = reinterpret_cast<const int4*>(src) + (size_t)idx * 2;
    int4 v0 = __ldg(&s[0]);
    int4 v1 = __ldg(&s[1]);
    uint32_t p[4];
    #define PK(lo_, hi_) \
        ((uint32_t)__half_as_ushort(__int2half_rn(lo_)) | \
         ((uint32_t)__half_as_ushort(__int2half_rn(hi_)) << 16))
    p[0] = PK(v0.x, v0.y);
    p[1] = PK(v0.z, v0.w);
    p[2] = PK(v1.x, v1.y);
    p[3] = PK(v1.z, v1.w);
    #undef PK
    reinterpret_cast<uint4*>(dst)[idx] = make_uint4(p[0], p[1], p[2], p[3]);
}

// ---------------------------------------------------------------- GEMM
// 4 warps: 2 in M (32 rows) x 2 in N (64 cols).  Warp tile 32x64.
__global__ void __launch_bounds__(NTHREADS, 3)
w8a8_hmma_kernel(const float* __restrict__ bias, float* __restrict__ out) {
    extern __shared__ char smem[];
    const uint32_t sb = smem_u32(smem);
    const int tid  = threadIdx.x;
    const int wid  = tid >> 5;
    const int lane = tid & 31;

    const int n0 = blockIdx.x * N_TILE;
    const int m0 = blockIdx.y * M_TILE;

    float* rbias = reinterpret_cast<float*>(smem + SM_RBIAS);
    for (int j = tid; j < N_TILE; j += NTHREADS)
        rbias[j] = rintf(__ldg(&bias[n0 + j]));

    // ---- bases ----------------------------------------------------------
    const int wm = (wid & 1) * 32;          // M offset within tile
    const int wn = (wid >> 1) * 64;         // N offset within tile
    const int lrow = lane & 15;
    const uint32_t x7    = (uint32_t)((lane & 7) << 4);
    const uint32_t lch16 = (uint32_t)((lane >> 4) << 4);

    const uint32_t aBase = sb + SM_A + (uint32_t)((wm + lrow) * 128);
    const uint32_t bBase = sb + SM_B + (uint32_t)((wn + lrow) * 128);

    // per-warp k16 rotation (exact addition reorder)
    const int rot = wid & 3;
    uint32_t cxr[4];
    #pragma unroll
    for (int j = 0; j < 4; j++)
        cxr[j] = ((((uint32_t)((j + rot) & 3)) << 5) | lch16) ^ x7;

    // cp.async bases: thread handles rows row0+16i, fixed chunk c0
    const int row0 = tid >> 3, c0 = tid & 7;    // row0 in 0..15
    const uint32_t swz0 = (uint32_t)(row0 * 128 + ((c0 ^ (row0 & 7)) << 4));
    const uint32_t dstA0 = sb + SM_A + swz0;
    const uint32_t dstB0 = sb + SM_B + swz0;
    const __half* srcA0 = g_xh + (size_t)(m0 + row0) * K_DIM + c0 * 8;
    const __half* srcB0 = g_wh + (size_t)(n0 + row0) * K_DIM + c0 * 8;

    // A: 64 rows -> 4 iters of 16 rows; B: 128 rows -> 8 iters.
    // per-i: dst +16*128 = 2048B; src +16*4096 = 65536 halves
    #define LOAD_STAGE_S(s_, kofs_) do {                                      \
        _Pragma("unroll")                                                     \
        for (int i_ = 0; i_ < 4; i_++)                                        \
            cp16(dstA0 + (uint32_t)((s_) * A_STAGE_BYTES + i_ * 2048),        \
                 srcA0 + (kofs_) + i_ * 65536);                               \
        _Pragma("unroll")                                                     \
        for (int i_ = 0; i_ < 8; i_++)                                        \
            cp16(dstB0 + (uint32_t)((s_) * B_STAGE_BYTES + i_ * 2048),        \
                 srcB0 + (kofs_) + i_ * 65536);                               \
        cp_commit();                                                          \
    } while (0)

    float acc[2][8][4];
    #pragma unroll
    for (int mi = 0; mi < 2; mi++)
        #pragma unroll
        for (int ni = 0; ni < 8; ni++)
            #pragma unroll
            for (int r = 0; r < 4; r++) acc[mi][ni][r] = 0.f;

    uint32_t afr[2][2][4];      // ping-pong x 2 m16-blocks
    uint32_t bfr[2][4][4];      // ping-pong x 4 n16-groups

    #define LOAD_A2(pp_, s_, j_) do {                                         \
        ldsm4(afr[pp_][0], aBase + cxr[j_] +                                  \
              (uint32_t)((s_) * A_STAGE_BYTES + 0 * 2048));                   \
        ldsm4(afr[pp_][1], aBase + cxr[j_] +                                  \
              (uint32_t)((s_) * A_STAGE_BYTES + 1 * 2048));                   \
    } while (0)
    #define LOAD_B4(pp_, s_, j_) do {                                         \
        _Pragma("unroll")                                                     \
        for (int g_ = 0; g_ < 4; g_++)                                        \
            ldsm4(bfr[pp_][g_], bBase + cxr[j_] +                             \
                  (uint32_t)((s_) * B_STAGE_BYTES + g_ * 2048));              \
    } while (0)

    // one k16 sub-iteration: prefetch next kk's frags (or next stage's t0),
    // then 16 MMAs (2 mi x 8 ni).
    #define SUBIT(t_, s_, sn_, pf_) do {                                      \
        const int b_ = (t_) & 1;                                              \
        if ((t_) < 3) {                                                       \
            LOAD_A2(b_ ^ 1, s_, (t_) + 1);                                    \
            LOAD_B4(b_ ^ 1, s_, (t_) + 1);                                    \
        } else if (pf_) {                                                     \
            LOAD_A2(b_ ^ 1, sn_, 0);                                          \
            LOAD_B4(b_ ^ 1, sn_, 0);                                          \
        }                                                                     \
        _Pragma("unroll")                                                     \
        for (int mi_ = 0; mi_ < 2; mi_++)                                     \
            _Pragma("unroll")                                                 \
            for (int ni_ = 0; ni_ < 8; ni_++)                                 \
                mma_f16(acc[mi_][ni_], afr[b_][mi_],                          \
                        bfr[b_][ni_ >> 1][ni_ & 1],                           \
                        bfr[b_][ni_ >> 1][(ni_ & 1) + 2]);                    \
    } while (0)

    // ---- prologue --------------------------------------------------------
    LOAD_STAGE_S(0, 0);
    LOAD_STAGE_S(1, K_ELE);
    cp_wait0();
    __syncthreads();
    LOAD_A2(0, 0, 0);
    LOAD_B4(0, 0, 0);

    // ---- main loop: ks = 0..62 (unrolled by 3), tail ks = 63 --------------
    // Late barrier: subits 0..2 read stage j (published last iter); the
    // wait0+sync protect the cp16 overwrite of stage (j+2)%3 and the t=3
    // prefetch of stage (j+1)%3.
    int kload = 2 * K_ELE;
    for (int kb = 0; kb < (K_ITERS - 1) / 3; kb++) {
        #pragma unroll
        for (int j = 0; j < 3; j++) {
            SUBIT(0, j, (j + 1) % 3, 1);
            SUBIT(1, j, (j + 1) % 3, 1);
            SUBIT(2, j, (j + 1) % 3, 1);
            cp_wait0();
            __syncthreads();
            if (kload < K_DIM) {
                LOAD_STAGE_S((j + 2) % 3, kload);
                kload += K_ELE;
            }
            SUBIT(3, j, (j + 1) % 3, 1);
        }
    }
    // tail: ks = 63, stage 0 (t0 frags prefetched at ks=62's subit 3)
    SUBIT(0, 0, 1, 0);
    SUBIT(1, 0, 1, 0);
    SUBIT(2, 0, 1, 0);
    SUBIT(3, 0, 1, 0);

    // epilogue: c0,c1 at (row=lane>>2, col=(lane&3)*2+{0,1}); c2,c3 at row+8
    const int erow = lane >> 2;
    const int ecol = (lane & 3) * 2;
    #pragma unroll
    for (int mi = 0; mi < 2; mi++) {
        #pragma unroll
        for (int ni = 0; ni < 8; ni++) {
            const int gc = wn + ni * 8 + ecol;
            const float b0 = rbias[gc], b1 = rbias[gc + 1];
            {
                const int gr = m0 + wm + mi * 16 + erow;
                float2 v;
                v.x = acc[mi][ni][0] + b0;
                v.y = acc[mi][ni][1] + b1;
                *reinterpret_cast<float2*>(out + (size_t)gr * N_DIM + n0 + gc) = v;
            }
            {
                const int gr = m0 + wm + mi * 16 + 8 + erow;
                float2 v;
                v.x = acc[mi][ni][2] + b0;
                v.y = acc[mi][ni][3] + b1;
                *reinterpret_cast<float2*>(out + (size_t)gr * N_DIM + n0 + gc) = v;
            }
        }
    }
}

// ---------------------------------------------------------------- launch
extern "C" void kernel_launch(void* const* d_in, const int* in_sizes, int n_in,
                              void* d_out, int out_size) {
    int xi = 0, bi = 0;
    for (int i = 1; i < n_in; i++) {
        if (in_sizes[i] > in_sizes[xi]) xi = i;
        if (in_sizes[i] < in_sizes[bi]) bi = i;
    }
    int wi = 3 - xi - bi;

    const int*   x32  = (const int*)d_in[xi];
    const int*   w32  = (const int*)d_in[wi];
    const float* bias = (const float*)d_in[bi];
    float* out = (float*)d_out;

    __half* xh = nullptr; cudaGetSymbolAddress((void**)&xh, g_xh);
    __half* wh = nullptr; cudaGetSymbolAddress((void**)&wh, g_wh);

    const int n8x = (M_DIM * K_DIM) / 8;
    const int n8w = (N_DIM * K_DIM) / 8;
    const int n8t = n8x + n8w;
    pack_s32_to_f16<<<(n8t + 255) / 256, 256>>>(x32, w32, xh, wh, n8x, n8t);

    cudaFuncSetAttribute(w8a8_hmma_kernel,
                         cudaFuncAttributeMaxDynamicSharedMemorySize, SMEM_TOTAL);

    dim3 grid(N_DIM / N_TILE, M_DIM / M_TILE);         // (32, 128) = 4096 CTAs
    w8a8_hmma_kernel<<<grid, NTHREADS, SMEM_TOTAL>>>(bias, out);
}